// round 17
// baseline (speedup 1.0000x reference)
#include <cuda_runtime.h>
#include <cstdint>
#include <math.h>

#define HIDDEN   2048
#define NQ       8
#define HD       256
#define QKV_ROWS 2560   // (8 + 2) * 256
#define SEQ      8192
#define LAYER    5
#define CHUNK    32
#define NCHUNK   256    // SEQ / CHUNK
#define NCOMB    32     // combine blocks inside the fused output kernel

// ---------------- scratch (device globals; no allocation) ----------------
__device__ __align__(16) float g_qkv[QKV_ROWS];
__device__ __align__(16) float g_part[NCHUNK * NQ * HD];
__device__ __align__(16) float g_l[NCHUNK * NQ];
__device__ __align__(16) float g_attn[NQ * HD];
__device__ int g_done;                       // combine-completion counter

__device__ __forceinline__ float warp_sum(float v) {
#pragma unroll
    for (int o = 16; o; o >>= 1) v += __shfl_xor_sync(0xffffffffu, v, o);
    return v;
}
__device__ __forceinline__ float warp_max(float v) {
#pragma unroll
    for (int o = 16; o; o >>= 1) v = fmaxf(v, __shfl_xor_sync(0xffffffffu, v, o));
    return v;
}
__device__ __forceinline__ float dot4(float4 a, float4 b) {
    return a.x * b.x + a.y * b.y + a.z * b.z + a.w * b.w;
}

// ---------------- qkv GEMV: 1 row / 128-thread block (R16 proven) ----------
// Also resets g_done for the fused output kernel (strictly earlier launch).
__global__ void __launch_bounds__(128)
gemv_qkv_kernel(const float* __restrict__ W,
                const float* __restrict__ x,
                float* __restrict__ y) {
    if (blockIdx.x == 0 && threadIdx.x == 0) g_done = 0;

    int t = threadIdx.x;
    int row = blockIdx.x;
    const float4* Wr = reinterpret_cast<const float4*>(W + (size_t)row * HIDDEN);
    const float4* x4 = reinterpret_cast<const float4*>(x);

    float4 w0 = __ldcs(&Wr[t]);
    float4 w1 = __ldcs(&Wr[t + 128]);
    float4 w2 = __ldcs(&Wr[t + 256]);
    float4 w3 = __ldcs(&Wr[t + 384]);
    float4 v0 = __ldg(&x4[t]);
    float4 v1 = __ldg(&x4[t + 128]);
    float4 v2 = __ldg(&x4[t + 256]);
    float4 v3 = __ldg(&x4[t + 384]);

    float acc = dot4(w0, v0) + dot4(w1, v1) + dot4(w2, v2) + dot4(w3, v3);
    acc = warp_sum(acc);

    __shared__ float swarp[4];
    int warp = t >> 5, lane = t & 31;
    if (lane == 0) swarp[warp] = acc;
    __syncthreads();
    if (t == 0)
        y[row] = swarp[0] + swarp[1] + swarp[2] + swarp[3];
}

// ---------------- fused attention (512 threads, R12 config — proven) -------
__global__ void __launch_bounds__(512, 2)
fused_attn_kernel(const float* __restrict__ kc,
                  const float* __restrict__ vc,
                  const float* __restrict__ mask,
                  const float* __restrict__ cosv,
                  const float* __restrict__ sinv,
                  const float* __restrict__ qw,
                  const float* __restrict__ kw,
                  const int* __restrict__ kvidx) {
    __shared__ float sq[NQ * HD];
    __shared__ float sk[HD];
    __shared__ float sexp[CHUNK * NQ];
    __shared__ float smask[CHUNK];
    __shared__ float sup[NQ][HD];
    __shared__ int   sany;

    int c    = blockIdx.x;
    int tid  = threadIdx.x;
    int warp = tid >> 5, lane = tid & 31;
    int s0   = c * CHUNK;

    if (tid == 0) sany = 0;
    __syncthreads();
    if (tid < CHUNK) {
        float m = mask[s0 + tid];
        smask[tid] = m;
        if (m > -1e8f) atomicOr(&sany, 1);
    }
    __syncthreads();
    if (!sany) {
        if (tid < NQ) g_l[c * NQ + tid] = 0.0f;
        return;
    }

    if (warp < 9) {
        int head = warp;
        float x[8];
#pragma unroll
        for (int j = 0; j < 8; j++) x[j] = g_qkv[head * HD + lane + 32 * j];
        float mv = 0.f;
#pragma unroll
        for (int j = 0; j < 8; j++) mv = fmaxf(mv, fabsf(x[j]));
        mv = warp_max(mv);
        mv = fmaxf(mv, 5.9604644775390625e-8f);   // 2^-24
        float ss = 0.f, xs[8];
#pragma unroll
        for (int j = 0; j < 8; j++) { xs[j] = x[j] / mv; ss += xs[j] * xs[j]; }
        ss = warp_sum(ss);
        float rs = rsqrtf(ss);
        const float* wv = (head < NQ) ? qw : kw;
        float y[8];
#pragma unroll
        for (int j = 0; j < 8; j++) {
            int d = lane + 32 * j;
            y[j] = rs * 16.0f * xs[j] * (1.0f + wv[d]);
        }
#pragma unroll
        for (int j = 0; j < 8; j++) {
            int d = lane + 32 * j;
            float rot = (j < 4) ? -y[j ^ 4] : y[j ^ 4];
            float out = y[j] * cosv[d] + rot * sinv[d];
            if (head < NQ) sq[head * HD + d] = out * 0.0625f;  // * 256^-0.5
            else           sk[d] = out;
        }
    }
    __syncthreads();

    int pos = *kvidx;
    const float* kbase = kc + (size_t)LAYER * SEQ * HD;

    {
        float acc[2][NQ];
        const float4* k4p[2];
#pragma unroll
        for (int r = 0; r < 2; r++) {
            int sl = warp * 2 + r;
            int s = s0 + sl;
            const float* krow = (s == pos) ? sk : (kbase + (size_t)s * HD);
            k4p[r] = reinterpret_cast<const float4*>(krow);
#pragma unroll
            for (int h = 0; h < NQ; h++) acc[r][h] = 0.f;
        }
#pragma unroll
        for (int i = 0; i < 2; i++) {
            int idx = i * 32 + lane;
            float4 kv0 = k4p[0][idx];
            float4 kv1 = k4p[1][idx];
#pragma unroll
            for (int h = 0; h < NQ; h++) {
                const float4* q4 = reinterpret_cast<const float4*>(&sq[h * HD]);
                float4 qv = q4[idx];
                acc[0][h] += dot4(kv0, qv);
                acc[1][h] += dot4(kv1, qv);
            }
        }
#pragma unroll
        for (int r = 0; r < 2; r++) {
            int sl = warp * 2 + r;
            float m = smask[sl];
#pragma unroll
            for (int h = 0; h < NQ; h++) {
                float v = warp_sum(acc[r][h]);
                if (lane == h)
                    sexp[sl * NQ + h] = (m < -1e8f) ? 0.0f
                                      : expf(tanhf(v * 0.02f) * 50.0f + m);
            }
        }
    }
    __syncthreads();

    if (warp < NQ) {
        float l = sexp[lane * NQ + warp];
        l = warp_sum(l);
        if (lane == 0) g_l[c * NQ + warp] = l;
    }

    const float* vbase = vc + (size_t)LAYER * SEQ * HD;
    const float* vnew  = g_qkv + 9 * HD;
    int grp = tid >> 8;
    int d   = tid & 255;
    float acc[NQ] = {0, 0, 0, 0, 0, 0, 0, 0};
#pragma unroll 8
    for (int k = 0; k < CHUNK / 2; k++) {
        int sl = grp * (CHUNK / 2) + k;
        int s = s0 + sl;
        float v = (s == pos) ? vnew[d] : __ldcs(&vbase[(size_t)s * HD + d]);
#pragma unroll
        for (int h = 0; h < NQ; h++) acc[h] += sexp[sl * NQ + h] * v;
    }
    if (grp == 1) {
#pragma unroll
        for (int h = 0; h < NQ; h++) sup[h][d] = acc[h];
    }
    __syncthreads();
    if (grp == 0) {
#pragma unroll
        for (int h = 0; h < NQ; h++)
            g_part[(c * NQ + h) * HD + d] = acc[h] + sup[h][d];
    }
}

// ---------------- fused combine + output GEMV -------------------------------
// Blocks 0..31: combine (h = bid>>2, 64-d slice = bid&3), then count up.
// Blocks 32..2079: one o_w row each. They issue all 8 W loads FIRST (no
// dependency), spin until combine completes, then read g_attn (L2-hot)
// and finish. Removes one launch boundary and hides combine latency under
// the W-load stream.
__global__ void __launch_bounds__(128)
fused_out_kernel(const float* __restrict__ W,
                 float* __restrict__ y) {
    int bid = blockIdx.x;
    int t   = threadIdx.x;

    if (bid < NCOMB) {
        // ---- combine block ----
        int h  = bid >> 2;
        int d0 = (bid & 3) * 64;
        int g  = t >> 6;           // chunk-parity group 0/1
        int dl = t & 63;
        int d  = d0 + dl;

        __shared__ float sl[NCHUNK];
        sl[t]       = g_l[t * NQ + h];
        sl[t + 128] = g_l[(t + 128) * NQ + h];
        __syncthreads();

        float acc = 0.f, L = 0.f;
#pragma unroll 16
        for (int k = 0; k < NCHUNK / 2; k++) {
            int c = g + 2 * k;
            float l = sl[c];
            if (l > 0.f) {
                L += l;
                acc += g_part[(c * NQ + h) * HD + d];
            }
        }
        __shared__ float sacc[2][64];
        __shared__ float sLr[2][64];
        sacc[g][dl] = acc;
        sLr[g][dl]  = L;
        __syncthreads();
        if (g == 0)
            g_attn[h * HD + d] = (sacc[0][dl] + sacc[1][dl]) /
                                 (sLr[0][dl] + sLr[1][dl]);
        __threadfence();
        __syncthreads();
        if (t == 0) atomicAdd(&g_done, 1);
        return;
    }

    // ---- output GEMV block ----
    int row = bid - NCOMB;
    const float4* Wr = reinterpret_cast<const float4*>(W + (size_t)row * HIDDEN);

    // W loads have no dependency on combine: issue immediately.
    float4 w0 = __ldcs(&Wr[t]);
    float4 w1 = __ldcs(&Wr[t + 128]);
    float4 w2 = __ldcs(&Wr[t + 256]);
    float4 w3 = __ldcs(&Wr[t + 384]);

    // Wait for combine (g_attn) — W loads remain in flight meanwhile.
    if (t == 0) {
        while (*((volatile int*)&g_done) < NCOMB) __nanosleep(32);
    }
    __syncthreads();
    __threadfence();

    const float4* x4 = reinterpret_cast<const float4*>(g_attn);
    float4 v0 = x4[t];
    float4 v1 = x4[t + 128];
    float4 v2 = x4[t + 256];
    float4 v3 = x4[t + 384];

    float acc = dot4(w0, v0) + dot4(w1, v1) + dot4(w2, v2) + dot4(w3, v3);
    acc = warp_sum(acc);

    __shared__ float swarp[4];
    int warp = t >> 5, lane = t & 31;
    if (lane == 0) swarp[warp] = acc;
    __syncthreads();
    if (t == 0)
        y[row] = swarp[0] + swarp[1] + swarp[2] + swarp[3];
}

// ---------------- launch ----------------------------------------------------
extern "C" void kernel_launch(void* const* d_in, const int* in_sizes, int n_in,
                              void* d_out, int out_size) {
    const float* hs   = (const float*)d_in[0];   // hidden_states (2048)
    const float* cosv = (const float*)d_in[1];   // cos (256)
    const float* sinv = (const float*)d_in[2];   // sin (256)
    const int*   kvix = (const int*)  d_in[3];   // kv_write_indices (1)
    const float* kc   = (const float*)d_in[4];   // k_cache
    const float* vc   = (const float*)d_in[5];   // v_cache
    const float* mask = (const float*)d_in[6];   // mask (8192)
    const float* qkvw = (const float*)d_in[7];   // qkv_w (2560x2048)
    const float* ow   = (const float*)d_in[8];   // o_w   (2048x2048)
    const float* qnw  = (const float*)d_in[9];   // q_norm_w (256)
    const float* knw  = (const float*)d_in[10];  // k_norm_w (256)
    float* out = (float*)d_out;

    void* p_qkv = nullptr;
    cudaGetSymbolAddress(&p_qkv, g_qkv);

    gemv_qkv_kernel<<<QKV_ROWS, 128>>>(qkvw, hs, (float*)p_qkv);
    fused_attn_kernel<<<NCHUNK, 512>>>(kc, vc, mask, cosv, sinv, qnw, knw, kvix);
    fused_out_kernel<<<HIDDEN + NCOMB, 128>>>(ow, out);
}